// round 1
// baseline (speedup 1.0000x reference)
#include <cuda_runtime.h>

// Problem constants (fixed by reference setup_inputs)
#define M_ROWS  200000      // BATCH * SIM_T
#define K_DIM   784
#define N1      100
#define T_STEPS 2000
#define BATCH   100
#define N2      10

// Scratch for z1 = batch @ W1^T  (200000 x 100 fp32 = 80 MB)
__device__ float g_z1[(size_t)M_ROWS * N1];

// ---------------------------------------------------------------------------
// GEMM: C[M,100] = A[M,784] * W1[100,784]^T   (fp32 exact, f32x2 packed FFMA)
// ---------------------------------------------------------------------------
#define BM 128
#define BN 112   // padded N (only 100 valid)
#define BK 16
#define TM 8
#define TN 7
#define AS_STRIDE 132
#define BS_STRIDE 113

__global__ void __launch_bounds__(256, 2)
gemm_z1_kernel(const float* __restrict__ A, const float* __restrict__ W1) {
    __shared__ __align__(16) float As[BK][AS_STRIDE];   // As[k][m]
    __shared__ __align__(16) float Bs[BK][BS_STRIDE];   // Bs[k][n]

    const int tid = threadIdx.x;
    const int tx  = tid & 15;     // column group: cols tx*7 .. tx*7+6
    const int ty  = tid >> 4;     // row group:    rows ty*8 .. ty*8+7
    const int row0 = blockIdx.x * BM;

    // accumulators: 4 row-pairs x 7 cols, packed f32x2 (lo = even row)
    unsigned long long acc[4][TN];
#pragma unroll
    for (int i = 0; i < 4; i++)
#pragma unroll
        for (int j = 0; j < TN; j++) acc[i][j] = 0ull;

    const int a_row = tid >> 2;           // 0..63
    const int a_k4  = (tid & 3) << 2;     // 0,4,8,12

    for (int k0 = 0; k0 < K_DIM; k0 += BK) {
        // --- load A tile (128 x 16), transposed into As[k][m] ---
#pragma unroll
        for (int rr = 0; rr < 2; rr++) {
            int r = row0 + a_row + rr * 64;
            float4 v = make_float4(0.f, 0.f, 0.f, 0.f);
            if (r < M_ROWS)
                v = *(const float4*)(A + (size_t)r * K_DIM + k0 + a_k4);
            As[a_k4 + 0][a_row + rr * 64] = v.x;
            As[a_k4 + 1][a_row + rr * 64] = v.y;
            As[a_k4 + 2][a_row + rr * 64] = v.z;
            As[a_k4 + 3][a_row + rr * 64] = v.w;
        }
        // --- load B tile (112 x 16): Bs[k][n] = W1[n][k0+k], zero-pad n>=100 ---
#pragma unroll
        for (int i = 0; i < 7; i++) {
            int idx = i * 256 + tid;        // 0..1791
            int nn  = idx >> 4;
            int kk  = idx & 15;
            Bs[kk][nn] = (nn < N1) ? W1[nn * K_DIM + k0 + kk] : 0.f;
        }
        __syncthreads();

#pragma unroll
        for (int k = 0; k < BK; k++) {
            unsigned long long a64[4];
            const unsigned long long* ap =
                reinterpret_cast<const unsigned long long*>(&As[k][ty * TM]);
#pragma unroll
            for (int i = 0; i < 4; i++) a64[i] = ap[i];
#pragma unroll
            for (int j = 0; j < TN; j++) {
                unsigned int bu = __float_as_uint(Bs[k][tx * TN + j]);
                unsigned long long b64;
                asm("mov.b64 %0, {%1, %1};" : "=l"(b64) : "r"(bu));
#pragma unroll
                for (int i = 0; i < 4; i++)
                    asm("fma.rn.f32x2 %0, %1, %2, %0;"
                        : "+l"(acc[i][j]) : "l"(a64[i]), "l"(b64));
            }
        }
        __syncthreads();
    }

    // --- store ---
#pragma unroll
    for (int i = 0; i < 4; i++) {
#pragma unroll
        for (int j = 0; j < TN; j++) {
            int nn = tx * TN + j;
            if (nn >= N1) continue;
            int r = row0 + ty * TM + 2 * i;
            float vx = __uint_as_float((unsigned int)(acc[i][j] & 0xffffffffull));
            float vy = __uint_as_float((unsigned int)(acc[i][j] >> 32));
            if (r < M_ROWS)     g_z1[(size_t)r * N1 + nn]       = vx;
            if (r + 1 < M_ROWS) g_z1[(size_t)(r + 1) * N1 + nn] = vy;
        }
    }
}

// ---------------------------------------------------------------------------
// Fused HH: layer-1 (100 neurons) + matvec z2 + layer-2 (10 neurons), pipelined
// ---------------------------------------------------------------------------
__device__ __forceinline__ float gate_upd(float a, float b, float g) {
    float s = 0.005f * (a + b);
    return (a * 0.01f + (1.f - s) * g) / (s + 1.f);
}

__device__ __forceinline__ void hh_step(float zk, float& V, float& m, float& n, float& h) {
    float m2   = m * m;
    float pow1 = 40.f * (m2 * m) * h;
    float n2   = n * n;
    float pow2 = 35.f * (n2 * n2);
    float Gs = 0.005f * (pow1 + pow2 + 0.3f);
    float E  = pow1 * 55.f + pow2 * (-77.f) + 0.3f * (-65.f);
    float Vn = (V * (1.f - Gs) + 0.01f * (E + 1.5f + zk)) / (1.f + Gs);

    const float C9  = 1.f / 9.f;
    const float C12 = 1.f / 12.f;
    float aN =  0.02f  * (Vn - 25.f) / (1.f - expf((25.f - Vn) * C9));
    float bN = -0.002f * (Vn - 25.f) / (1.f - expf((Vn - 25.f) * C9));
    float aM =  0.182f * (Vn + 35.f) / (1.f - expf((-Vn - 35.f) * C9));
    float bM = -0.124f * (Vn + 35.f) / (1.f - expf((Vn + 35.f) * C9));
    float aH =  0.25f * expf((-Vn - 90.f) * C12);
    float bH =  0.25f * expf((Vn + 34.f) * C12);
    if (Vn == 25.f)  { aN = 0.18f;  bN = 0.018f; }
    if (Vn == -35.f) { aM = 1.638f; bM = 1.116f; }

    m = gate_upd(aM, bM, m);
    n = gate_upd(aN, bN, n);
    h = gate_upd(aH, bH, h);
    V = Vn;
}

__device__ __forceinline__ float sigmoid_T(float V) {
    // sigmoid((V - 20)/3)
    return 1.f / (1.f + expf((20.f - V) * (1.f / 3.f)));
}

__global__ void __launch_bounds__(256, 1)
hh_fused_kernel(const float* __restrict__ W2, float* __restrict__ out) {
    __shared__ float T1buf[2][104];   // padded to 104 (entries 100..103 stay 0)
    __shared__ float z2buf[2][16];

    const int b   = blockIdx.x;
    const int tid = threadIdx.x;
    const float S0 = 1.f / (1.f + expf(30.f));   // sigmoid((-70-20)/3)

    // Shared neuron state registers (used by G1 threads and G3 threads)
    float V = -70.f, m = 0.f, n = 0.f, h = 1.f;

    // G1 prefetch queue
    float p0 = 0.f, p1 = 0.f, p2 = 0.f, p3 = 0.f;
    const float* zp = g_z1 + (size_t)b * T_STEPS * N1 + tid;

    // G2 weights
    float w[13];
    int g = 0, l = 0;

    // G3 output index
    const int o = tid - 224;

    if (tid < 100) {
        T1buf[0][tid] = S0;
        p0 = zp[0];
        p1 = zp[100];
        p2 = zp[200];
        p3 = zp[300];
    }
    if (tid < 8) {                       // zero the padding lanes of both buffers
        T1buf[tid >> 2][100 + (tid & 3)] = 0.f;
    }
    if (tid >= 128 && tid < 224) {       // matvec group: 12 groups of 8 (10 real)
        int u = tid - 128;
        g = u >> 3;
        l = u & 7;
#pragma unroll
        for (int i = 0; i < 13; i++) {
            int j = l + 8 * i;
            w[i] = (g < N2 && j < N1) ? W2[g * N1 + j] : 0.f;
        }
    }
    if (o >= 0 && o < N2) {              // T2 at t=0
        out[(size_t)b * T_STEPS * N2 + o] = S0;
    }
    __syncthreads();

    for (int t = 1; t < T_STEPS; ++t) {
        if (tid < 128) {
            // ---- G1: layer-1 neurons ----
            if (tid < 100) {
                float zc = p0;
                p0 = p1; p1 = p2; p2 = p3;
                p3 = (t <= T_STEPS - 5) ? zp[(size_t)(t + 3) * N1] : 0.f;
                hh_step(zc, V, m, n, h);
                T1buf[t & 1][tid] = sigmoid_T(V);
            }
        } else if (tid < 224) {
            // ---- G2: z2[t-1] = W2 @ T1[t-1] ----
            const float* tb = T1buf[(t - 1) & 1];
            float acc = 0.f;
#pragma unroll
            for (int i = 0; i < 13; i++)
                acc = fmaf(w[i], tb[l + 8 * i], acc);
            acc += __shfl_down_sync(0xffffffffu, acc, 4, 8);
            acc += __shfl_down_sync(0xffffffffu, acc, 2, 8);
            acc += __shfl_down_sync(0xffffffffu, acc, 1, 8);
            if (l == 0) z2buf[t & 1][g] = acc;
        } else {
            // ---- G3: layer-2 neurons, one step behind (computes V2[t-1]) ----
            if (o < N2 && t >= 2) {
                float zk = z2buf[(t - 1) & 1][o];   // = z2[t-2]
                hh_step(zk, V, m, n, h);
                out[(size_t)b * T_STEPS * N2 + (size_t)(t - 1) * N2 + o] = sigmoid_T(V);
            }
        }
        __syncthreads();
    }

    // Epilogue: V2[T-1] uses z2[T-2] (stored at iter T-1 into z2buf[(T-1)&1])
    if (o >= 0 && o < N2) {
        float zk = z2buf[(T_STEPS - 1) & 1][o];
        hh_step(zk, V, m, n, h);
        out[(size_t)b * T_STEPS * N2 + (size_t)(T_STEPS - 1) * N2 + o] = sigmoid_T(V);
    }
}

// ---------------------------------------------------------------------------
extern "C" void kernel_launch(void* const* d_in, const int* in_sizes, int n_in,
                              void* d_out, int out_size) {
    const float* batch = (const float*)d_in[0];   // (100, 2000, 784)
    const float* W1    = (const float*)d_in[1];   // (100, 784)
    const float* W2    = (const float*)d_in[2];   // (10, 100)
    float* out = (float*)d_out;                   // (100, 2000, 10)

    dim3 gemm_grid((M_ROWS + BM - 1) / BM);       // 1563
    gemm_z1_kernel<<<gemm_grid, 256>>>(batch, W1);
    hh_fused_kernel<<<BATCH, 256>>>(W2, out);
}

// round 2
// speedup vs baseline: 1.1622x; 1.1622x over previous
#include <cuda_runtime.h>

// Problem constants (fixed by reference setup_inputs)
#define M_ROWS  200000      // BATCH * SIM_T
#define K_DIM   784
#define N1      100
#define T_STEPS 2000
#define BATCH   100
#define N2      10

// Scratch for z1 = batch @ W1^T  (200000 x 100 fp32 = 80 MB)
__device__ float g_z1[(size_t)M_ROWS * N1];

// ---------------------------------------------------------------------------
// GEMM: C[M,100] = A[M,784] * W1[100,784]^T   (fp32 exact, f32x2 packed FFMA)
// (unchanged from round 1 — known good, ~835us; tensor-core rewrite next round)
// ---------------------------------------------------------------------------
#define BM 128
#define BN 112
#define BK 16
#define TM 8
#define TN 7
#define AS_STRIDE 132
#define BS_STRIDE 113

__global__ void __launch_bounds__(256, 2)
gemm_z1_kernel(const float* __restrict__ A, const float* __restrict__ W1) {
    __shared__ __align__(16) float As[BK][AS_STRIDE];   // As[k][m]
    __shared__ __align__(16) float Bs[BK][BS_STRIDE];   // Bs[k][n]

    const int tid = threadIdx.x;
    const int tx  = tid & 15;
    const int ty  = tid >> 4;
    const int row0 = blockIdx.x * BM;

    unsigned long long acc[4][TN];
#pragma unroll
    for (int i = 0; i < 4; i++)
#pragma unroll
        for (int j = 0; j < TN; j++) acc[i][j] = 0ull;

    const int a_row = tid >> 2;
    const int a_k4  = (tid & 3) << 2;

    for (int k0 = 0; k0 < K_DIM; k0 += BK) {
#pragma unroll
        for (int rr = 0; rr < 2; rr++) {
            int r = row0 + a_row + rr * 64;
            float4 v = make_float4(0.f, 0.f, 0.f, 0.f);
            if (r < M_ROWS)
                v = *(const float4*)(A + (size_t)r * K_DIM + k0 + a_k4);
            As[a_k4 + 0][a_row + rr * 64] = v.x;
            As[a_k4 + 1][a_row + rr * 64] = v.y;
            As[a_k4 + 2][a_row + rr * 64] = v.z;
            As[a_k4 + 3][a_row + rr * 64] = v.w;
        }
#pragma unroll
        for (int i = 0; i < 7; i++) {
            int idx = i * 256 + tid;
            int nn  = idx >> 4;
            int kk  = idx & 15;
            Bs[kk][nn] = (nn < N1) ? W1[nn * K_DIM + k0 + kk] : 0.f;
        }
        __syncthreads();

#pragma unroll
        for (int k = 0; k < BK; k++) {
            unsigned long long a64[4];
            const unsigned long long* ap =
                reinterpret_cast<const unsigned long long*>(&As[k][ty * TM]);
#pragma unroll
            for (int i = 0; i < 4; i++) a64[i] = ap[i];
#pragma unroll
            for (int j = 0; j < TN; j++) {
                unsigned int bu = __float_as_uint(Bs[k][tx * TN + j]);
                unsigned long long b64;
                asm("mov.b64 %0, {%1, %1};" : "=l"(b64) : "r"(bu));
#pragma unroll
                for (int i = 0; i < 4; i++)
                    asm("fma.rn.f32x2 %0, %1, %2, %0;"
                        : "+l"(acc[i][j]) : "l"(a64[i]), "l"(b64));
            }
        }
        __syncthreads();
    }

#pragma unroll
    for (int i = 0; i < 4; i++) {
#pragma unroll
        for (int j = 0; j < TN; j++) {
            int nn = tx * TN + j;
            if (nn >= N1) continue;
            int r = row0 + ty * TM + 2 * i;
            float vx = __uint_as_float((unsigned int)(acc[i][j] & 0xffffffffull));
            float vy = __uint_as_float((unsigned int)(acc[i][j] >> 32));
            if (r < M_ROWS)     g_z1[(size_t)r * N1 + nn]       = vx;
            if (r + 1 < M_ROWS) g_z1[(size_t)(r + 1) * N1 + nn] = vy;
        }
    }
}

// ---------------------------------------------------------------------------
// Fast approximate primitives (MUFU-based, ~2^-22 rel err)
// ---------------------------------------------------------------------------
__device__ __forceinline__ float ex2a(float x) {
    float r; asm("ex2.approx.f32 %0, %1;" : "=f"(r) : "f"(x)); return r;
}
__device__ __forceinline__ float rcpa(float x) {
    float r; asm("rcp.approx.f32 %0, %1;" : "=f"(r) : "f"(x)); return r;
}

// log2(e)/9, /12, /3
#define L9  0.1602994489863f
#define L12 0.1202245867397f
#define L3  0.4808983469589f
// 0.25 * exp(-56/12)
#define BH_C 0.0023508962f

__device__ __forceinline__ float gate_upd(float a, float b, float g) {
    float s = 0.005f * (a + b);
    return (fmaf(a, 0.01f, (1.f - s) * g)) * rcpa(s + 1.f);
}

__device__ __forceinline__ void hh_step(float zk, float& V, float& m, float& n, float& h) {
    float m2   = m * m;
    float pow1 = 40.f * (m2 * m) * h;
    float n2   = n * n;
    float pow2 = 35.f * (n2 * n2);
    float Gs = 0.005f * (pow1 + pow2 + 0.3f);
    float E  = fmaf(pow1, 55.f, fmaf(pow2, -77.f, -19.5f));   // gl*El = -19.5
    float num = fmaf(V, (1.f - Gs), 0.01f * (E + 1.5f + zk));
    float Vn = num * rcpa(1.f + Gs);

    // N gate rates: u = exp((Vn-25)/9); aN = 0.02 d u/(u-1); bN = 0.002 d/(u-1)
    float d25 = Vn - 25.f;
    float uN  = ex2a(d25 * L9);
    float rN  = rcpa(uN - 1.f);
    float aN  = 0.02f * d25 * uN * rN;
    float bN  = 0.002f * d25 * rN;

    // M gate rates: u = exp((Vn+35)/9); aM = 0.182 d u/(u-1); bM = 0.124 d/(u-1)
    float d35 = Vn + 35.f;
    float uM  = ex2a(d35 * L9);
    float rM  = rcpa(uM - 1.f);
    float aM  = 0.182f * d35 * uM * rM;
    float bM  = 0.124f * d35 * rM;

    // H gate rates: w = exp((Vn+90)/12); aH = 0.25/w; bH = 0.25 e^{-56/12} w
    float w  = ex2a((Vn + 90.f) * L12);
    float aH = 0.25f * rcpa(w);
    float bH = BH_C * w;

    if (Vn == 25.f)  { aN = 0.18f;  bN = 0.018f; }
    if (Vn == -35.f) { aM = 1.638f; bM = 1.116f; }

    m = gate_upd(aM, bM, m);
    n = gate_upd(aN, bN, n);
    h = gate_upd(aH, bH, h);
    V = Vn;
}

__device__ __forceinline__ float sigmoid_T(float V) {
    // sigmoid((V-20)/3) = 1 / (1 + exp((20-V)/3))
    return rcpa(1.f + ex2a((20.f - V) * L3));
}

// ---------------------------------------------------------------------------
// Fused HH: layer-1 (100 neurons) + matvec z2 + layer-2 (10 neurons), pipelined
// ---------------------------------------------------------------------------
__global__ void __launch_bounds__(256, 1)
hh_fused_kernel(const float* __restrict__ W2, float* __restrict__ out) {
    __shared__ float T1buf[2][104];
    __shared__ float z2buf[2][16];

    const int b   = blockIdx.x;
    const int tid = threadIdx.x;
    const float S0 = 9.357622969e-14f;   // sigmoid((-70-20)/3) = 1/(1+e^30)

    float V = -70.f, m = 0.f, n = 0.f, h = 1.f;

    float p0 = 0.f, p1 = 0.f, p2 = 0.f, p3 = 0.f;
    const float* zp = g_z1 + (size_t)b * T_STEPS * N1 + tid;

    float w[13];
    int g = 0, l = 0;
    const int o = tid - 224;

    if (tid < 100) {
        T1buf[0][tid] = S0;
        p0 = zp[0];
        p1 = zp[100];
        p2 = zp[200];
        p3 = zp[300];
    }
    if (tid < 8) {
        T1buf[tid >> 2][100 + (tid & 3)] = 0.f;
    }
    if (tid >= 128 && tid < 224) {
        int u = tid - 128;
        g = u >> 3;
        l = u & 7;
#pragma unroll
        for (int i = 0; i < 13; i++) {
            int j = l + 8 * i;
            w[i] = (g < N2 && j < N1) ? W2[g * N1 + j] : 0.f;
        }
    }
    if (o >= 0 && o < N2) {
        out[(size_t)b * T_STEPS * N2 + o] = S0;
    }
    __syncthreads();

    for (int t = 1; t < T_STEPS; ++t) {
        if (tid < 128) {
            if (tid < 100) {
                float zc = p0;
                p0 = p1; p1 = p2; p2 = p3;
                p3 = (t <= T_STEPS - 5) ? zp[(size_t)(t + 3) * N1] : 0.f;
                hh_step(zc, V, m, n, h);
                T1buf[t & 1][tid] = sigmoid_T(V);
            }
        } else if (tid < 224) {
            const float* tb = T1buf[(t - 1) & 1];
            float acc = 0.f;
#pragma unroll
            for (int i = 0; i < 13; i++)
                acc = fmaf(w[i], tb[l + 8 * i], acc);
            acc += __shfl_down_sync(0xffffffffu, acc, 4, 8);
            acc += __shfl_down_sync(0xffffffffu, acc, 2, 8);
            acc += __shfl_down_sync(0xffffffffu, acc, 1, 8);
            if (l == 0) z2buf[t & 1][g] = acc;
        } else {
            if (o < N2 && t >= 2) {
                float zk = z2buf[(t - 1) & 1][o];
                hh_step(zk, V, m, n, h);
                out[(size_t)b * T_STEPS * N2 + (size_t)(t - 1) * N2 + o] = sigmoid_T(V);
            }
        }
        __syncthreads();
    }

    if (o >= 0 && o < N2) {
        float zk = z2buf[(T_STEPS - 1) & 1][o];
        hh_step(zk, V, m, n, h);
        out[(size_t)b * T_STEPS * N2 + (size_t)(T_STEPS - 1) * N2 + o] = sigmoid_T(V);
    }
}

// ---------------------------------------------------------------------------
extern "C" void kernel_launch(void* const* d_in, const int* in_sizes, int n_in,
                              void* d_out, int out_size) {
    const float* batch = (const float*)d_in[0];   // (100, 2000, 784)
    const float* W1    = (const float*)d_in[1];   // (100, 784)
    const float* W2    = (const float*)d_in[2];   // (10, 100)
    float* out = (float*)d_out;                   // (100, 2000, 10)

    dim3 gemm_grid((M_ROWS + BM - 1) / BM);
    gemm_z1_kernel<<<gemm_grid, 256>>>(batch, W1);
    hh_fused_kernel<<<BATCH, 256>>>(W2, out);
}

// round 3
// speedup vs baseline: 1.2743x; 1.0965x over previous
#include <cuda_runtime.h>

// Problem constants
#define M_ROWS  200000      // BATCH * SIM_T
#define K_DIM   784
#define N1      100
#define T_STEPS 2000
#define BATCH   100
#define N2      10

// Scratch
__device__ float g_z1[(size_t)M_ROWS * N1];                 // 80 MB
__device__ float g_T1[(size_t)M_ROWS * N1];                 // 80 MB
__device__ float g_z2t[(size_t)BATCH * N2 * T_STEPS];       // 8 MB, [b*10+o][t]

// ---------------------------------------------------------------------------
// K1 GEMM: z1[M,100] = A[M,784] * W1[100,784]^T  (fp32 exact, f32x2 FFMA)
// ---------------------------------------------------------------------------
#define BM 128
#define BK 16
#define TM 8
#define TN 7
#define AS_STRIDE 132
#define BS_STRIDE 113

__global__ void __launch_bounds__(256, 2)
gemm_z1_kernel(const float* __restrict__ A, const float* __restrict__ W1) {
    __shared__ __align__(16) float As[BK][AS_STRIDE];
    __shared__ __align__(16) float Bs[BK][BS_STRIDE];

    const int tid = threadIdx.x;
    const int tx  = tid & 15;
    const int ty  = tid >> 4;
    const int row0 = blockIdx.x * BM;

    unsigned long long acc[4][TN];
#pragma unroll
    for (int i = 0; i < 4; i++)
#pragma unroll
        for (int j = 0; j < TN; j++) acc[i][j] = 0ull;

    const int a_row = tid >> 2;
    const int a_k4  = (tid & 3) << 2;

    for (int k0 = 0; k0 < K_DIM; k0 += BK) {
#pragma unroll
        for (int rr = 0; rr < 2; rr++) {
            int r = row0 + a_row + rr * 64;
            float4 v = make_float4(0.f, 0.f, 0.f, 0.f);
            if (r < M_ROWS)
                v = *(const float4*)(A + (size_t)r * K_DIM + k0 + a_k4);
            As[a_k4 + 0][a_row + rr * 64] = v.x;
            As[a_k4 + 1][a_row + rr * 64] = v.y;
            As[a_k4 + 2][a_row + rr * 64] = v.z;
            As[a_k4 + 3][a_row + rr * 64] = v.w;
        }
#pragma unroll
        for (int i = 0; i < 7; i++) {
            int idx = i * 256 + tid;
            int nn  = idx >> 4;
            int kk  = idx & 15;
            Bs[kk][nn] = (nn < N1) ? W1[nn * K_DIM + k0 + kk] : 0.f;
        }
        __syncthreads();

#pragma unroll
        for (int k = 0; k < BK; k++) {
            unsigned long long a64[4];
            const unsigned long long* ap =
                reinterpret_cast<const unsigned long long*>(&As[k][ty * TM]);
#pragma unroll
            for (int i = 0; i < 4; i++) a64[i] = ap[i];
#pragma unroll
            for (int j = 0; j < TN; j++) {
                unsigned int bu = __float_as_uint(Bs[k][tx * TN + j]);
                unsigned long long b64;
                asm("mov.b64 %0, {%1, %1};" : "=l"(b64) : "r"(bu));
#pragma unroll
                for (int i = 0; i < 4; i++)
                    asm("fma.rn.f32x2 %0, %1, %2, %0;"
                        : "+l"(acc[i][j]) : "l"(a64[i]), "l"(b64));
            }
        }
        __syncthreads();
    }

#pragma unroll
    for (int i = 0; i < 4; i++) {
#pragma unroll
        for (int j = 0; j < TN; j++) {
            int nn = tx * TN + j;
            if (nn >= N1) continue;
            int r = row0 + ty * TM + 2 * i;
            float vx = __uint_as_float((unsigned int)(acc[i][j] & 0xffffffffull));
            float vy = __uint_as_float((unsigned int)(acc[i][j] >> 32));
            if (r < M_ROWS)     g_z1[(size_t)r * N1 + nn]       = vx;
            if (r + 1 < M_ROWS) g_z1[(size_t)(r + 1) * N1 + nn] = vy;
        }
    }
}

// ---------------------------------------------------------------------------
// HH step — single EX2 + single RCP per gate (algebraically exact rewrite)
// ---------------------------------------------------------------------------
__device__ __forceinline__ float ex2a(float x) {
    float r; asm("ex2.approx.f32 %0, %1;" : "=f"(r) : "f"(x)); return r;
}
__device__ __forceinline__ float rcpa(float x) {
    float r; asm("rcp.approx.f32 %0, %1;" : "=f"(r) : "f"(x)); return r;
}

#define L9   0.1602994489863f     // log2(e)/9
#define L12  0.1202245867397f     // log2(e)/12
#define L3   0.4808983469589f     // log2(e)/3
#define BH_C 0.0023508962f        // 0.25*exp(-56/12)
#define S0V  9.357622969e-14f     // sigmoid((-70-20)/3)

__device__ __forceinline__ void hh_step(float zk, float& V, float& m, float& n, float& h) {
    float mm   = m * m;
    float pow1 = 40.f * (mm * m) * h;
    float nn   = n * n;
    float pow2 = 35.f * (nn * nn);
    float Gs = 0.005f * (pow1 + pow2 + 0.3f);
    float E  = fmaf(pow1, 55.f, fmaf(pow2, -77.f, -19.5f));
    float num = fmaf(V, (1.f - Gs), 0.01f * (E + 1.5f + zk));
    float Vn = num * rcpa(1.f + Gs);

    // M gate: u = exp((Vn+35)/9); sigma = 0.005*d*(0.182u+0.124)
    // m' = (0.00182*d*u + (u-1-sigma)m) / (u-1+sigma)
    float dM = Vn + 35.f;
    float uM = ex2a(dM * L9);
    float um1M = uM - 1.f;
    float sM = 0.005f * dM * fmaf(0.182f, uM, 0.124f);
    float mN = fmaf(0.00182f * dM, uM, (um1M - sM) * m) * rcpa(um1M + sM);

    // N gate: u = exp((Vn-25)/9); sigma = 0.005*d*(0.02u+0.002)
    // n' = (0.0002*d*u + (u-1-sigma)n) / (u-1+sigma)
    float dN = Vn - 25.f;
    float uN = ex2a(dN * L9);
    float um1N = uN - 1.f;
    float sN = 0.005f * dN * fmaf(0.02f, uN, 0.002f);
    float nN = fmaf(0.0002f * dN, uN, (um1N - sN) * n) * rcpa(um1N + sN);

    // H gate: w = exp((Vn+90)/12); sigma = 0.00125 + 0.005*BH_C*w^2
    // h' = (0.0025 + (w - sigma)h) / (w + sigma)
    float w  = ex2a((Vn + 90.f) * L12);
    float sH = fmaf(0.005f * BH_C, w * w, 0.00125f);
    float hN = fmaf(w - sH, h, 0.0025f) * rcpa(w + sH);

    // singularity patches (exact constants, essentially never taken)
    if (Vn == 25.f)  nN = fmaf(0.99901f, n, 0.0018f) * (1.f / 1.00099f);
    if (Vn == -35.f) mN = fmaf(0.98623f, m, 0.01638f) * (1.f / 1.01377f);

    m = mN; n = nN; h = hN;
    V = Vn;
}

__device__ __forceinline__ float sigmoid_T(float V) {
    return rcpa(1.f + ex2a((20.f - V) * L3));
}

// ---------------------------------------------------------------------------
// K2: layer-1 scan. One thread per (batch, neuron) chain. No barriers.
// ---------------------------------------------------------------------------
__global__ void __launch_bounds__(128, 1)
hh_layer1_kernel() {
    const int idx = blockIdx.x * 128 + threadIdx.x;
    if (idx >= BATCH * N1) return;
    const int b = idx / N1;
    const int c = idx - b * N1;

    const float* zp = g_z1 + (size_t)b * T_STEPS * N1 + c;   // z1[b][t][c]
    float*       tp = g_T1 + (size_t)b * T_STEPS * N1 + c;   // T1[b][t][c]

    float V = -70.f, m = 0.f, n = 0.f, h = 1.f;
    tp[0] = S0V;

    // depth-4 scalar prefetch queue (stride 400B, coalesced across lanes)
    float p0 = zp[0];
    float p1 = zp[(size_t)1 * N1];
    float p2 = zp[(size_t)2 * N1];
    float p3 = zp[(size_t)3 * N1];

    // s = z index; step computes V_{s+1}; run padded to 2000, store guarded
    for (int s4 = 0; s4 < T_STEPS; s4 += 4) {
#pragma unroll
        for (int j = 0; j < 4; j++) {
            int s = s4 + j;
            float zc = p0;
            p0 = p1; p1 = p2; p2 = p3;
            int pf = s + 4;
            p3 = (pf < T_STEPS) ? zp[(size_t)pf * N1] : 0.f;
            hh_step(zc, V, m, n, h);
            if (s < T_STEPS - 1) tp[(size_t)(s + 1) * N1] = sigmoid_T(V);
        }
    }
}

// ---------------------------------------------------------------------------
// K3: z2t[b*10+o][t] = sum_k T1[b][t][k] * W2[o][k]
// ---------------------------------------------------------------------------
__global__ void __launch_bounds__(256, 4)
z2_kernel(const float* __restrict__ W2) {
    __shared__ float W2s[N1][12];   // [k][o], o padded to 12

    const int tid = threadIdx.x;
    for (int i = tid; i < N1 * 12; i += 256) {
        int k = i / 12, o = i - k * 12;
        W2s[k][o] = (o < N2) ? W2[o * N1 + k] : 0.f;
    }
    __syncthreads();

    const int row = blockIdx.x * 256 + tid;      // (b*2000 + t)
    if (row >= M_ROWS) return;
    const int b = row / T_STEPS;
    const int t = row - b * T_STEPS;

    const float4* tr = (const float4*)(g_T1 + (size_t)row * N1);
    float acc[12];
#pragma unroll
    for (int o = 0; o < 12; o++) acc[o] = 0.f;

#pragma unroll 5
    for (int k4 = 0; k4 < 25; k4++) {
        float4 tv = tr[k4];
        const float* tf = &tv.x;
#pragma unroll
        for (int kk = 0; kk < 4; kk++) {
            int k = k4 * 4 + kk;
            float4 w0 = *(const float4*)&W2s[k][0];
            float4 w1 = *(const float4*)&W2s[k][4];
            float4 w2 = *(const float4*)&W2s[k][8];
            float f = tf[kk];
            acc[0] = fmaf(f, w0.x, acc[0]);  acc[1] = fmaf(f, w0.y, acc[1]);
            acc[2] = fmaf(f, w0.z, acc[2]);  acc[3] = fmaf(f, w0.w, acc[3]);
            acc[4] = fmaf(f, w1.x, acc[4]);  acc[5] = fmaf(f, w1.y, acc[5]);
            acc[6] = fmaf(f, w1.z, acc[6]);  acc[7] = fmaf(f, w1.w, acc[7]);
            acc[8] = fmaf(f, w2.x, acc[8]);  acc[9] = fmaf(f, w2.y, acc[9]);
        }
    }
#pragma unroll
    for (int o = 0; o < N2; o++)
        g_z2t[((size_t)b * N2 + o) * T_STEPS + t] = acc[o];
}

// ---------------------------------------------------------------------------
// K4: layer-2 scan. One thread per (batch, output) chain. No barriers.
// ---------------------------------------------------------------------------
__global__ void __launch_bounds__(128, 1)
hh_layer2_kernel(float* __restrict__ out) {
    const int idx = blockIdx.x * 128 + threadIdx.x;
    if (idx >= BATCH * N2) return;
    const int b = idx / N2;
    const int o = idx - b * N2;

    const float4* zrow = (const float4*)(g_z2t + (size_t)idx * T_STEPS);
    float* op = out + ((size_t)b * T_STEPS) * N2 + o;

    float V = -70.f, m = 0.f, n = 0.f, h = 1.f;
    op[0] = S0V;

    // two-deep float4 prefetch (each float4 covers 4 steps)
    float4 buf0 = zrow[0];
    float4 buf1 = zrow[1];

    for (int g = 0; g < T_STEPS / 4; g++) {
        float zv[4] = {buf0.x, buf0.y, buf0.z, buf0.w};
        buf0 = buf1;
        buf1 = (g + 2 < T_STEPS / 4) ? zrow[g + 2] : make_float4(0.f, 0.f, 0.f, 0.f);
#pragma unroll
        for (int j = 0; j < 4; j++) {
            int s = g * 4 + j;
            hh_step(zv[j], V, m, n, h);
            if (s < T_STEPS - 1) op[(size_t)(s + 1) * N2] = sigmoid_T(V);
        }
    }
}

// ---------------------------------------------------------------------------
extern "C" void kernel_launch(void* const* d_in, const int* in_sizes, int n_in,
                              void* d_out, int out_size) {
    const float* batch = (const float*)d_in[0];   // (100, 2000, 784)
    const float* W1    = (const float*)d_in[1];   // (100, 784)
    const float* W2    = (const float*)d_in[2];   // (10, 100)
    float* out = (float*)d_out;                   // (100, 2000, 10)

    gemm_z1_kernel<<<(M_ROWS + BM - 1) / BM, 256>>>(batch, W1);
    hh_layer1_kernel<<<(BATCH * N1 + 127) / 128, 128>>>();
    z2_kernel<<<(M_ROWS + 255) / 256, 256>>>(W2);
    hh_layer2_kernel<<<(BATCH * N2 + 127) / 128, 128>>>(out);
}

// round 4
// speedup vs baseline: 1.8047x; 1.4163x over previous
#include <cuda_runtime.h>
#include <cuda_bf16.h>

// Problem constants
#define M_ROWS  200000      // BATCH * SIM_T
#define K_DIM   784
#define N1      100
#define T_STEPS 2000
#define BATCH   100
#define N2      10

// Scratch
__device__ float g_z1[(size_t)M_ROWS * N1];                 // 80 MB
__device__ float g_T1[(size_t)M_ROWS * N1];                 // 80 MB
__device__ float g_z2t[(size_t)BATCH * N2 * T_STEPS];       // 8 MB
__device__ __nv_bfloat16 g_W1h[112 * K_DIM];                // W1 hi split (rows 100-111 zero)
__device__ __nv_bfloat16 g_W1l[112 * K_DIM];                // W1 lo split

// ---------------------------------------------------------------------------
// helpers
// ---------------------------------------------------------------------------
__device__ __forceinline__ unsigned pack_bf16x2(float fhi, float flo) {
    unsigned r;
    asm("cvt.rn.bf16x2.f32 %0, %1, %2;" : "=r"(r) : "f"(fhi), "f"(flo));
    return r;
}
__device__ __forceinline__ void mma_bf16(float* c, const unsigned* a,
                                         unsigned b0, unsigned b1) {
    asm("mma.sync.aligned.m16n8k16.row.col.f32.bf16.bf16.f32 "
        "{%0,%1,%2,%3}, {%4,%5,%6,%7}, {%8,%9}, {%0,%1,%2,%3};"
        : "+f"(c[0]), "+f"(c[1]), "+f"(c[2]), "+f"(c[3])
        : "r"(a[0]), "r"(a[1]), "r"(a[2]), "r"(a[3]), "r"(b0), "r"(b1));
}

// ---------------------------------------------------------------------------
// K0: convert W1 (100x784 fp32) -> bf16 hi/lo, padded to 112 rows
// ---------------------------------------------------------------------------
__global__ void w1_convert_kernel(const float* __restrict__ W1) {
    int idx = blockIdx.x * 256 + threadIdx.x;
    if (idx >= 112 * K_DIM) return;
    int r = idx / K_DIM;
    float w = (r < N1) ? W1[idx - (r - r) * 0 + (r < N1 ? 0 : 0)] : 0.f; // placate
    w = (r < N1) ? W1[(size_t)r * K_DIM + (idx - r * K_DIM)] : 0.f;
    __nv_bfloat16 hb = __float2bfloat16_rn(w);
    float hf = __bfloat162float(hb);
    __nv_bfloat16 lb = __float2bfloat16_rn(w - hf);
    g_W1h[idx] = hb;
    g_W1l[idx] = lb;
}

// ---------------------------------------------------------------------------
// K1: tensor-core GEMM  z1[M,100] = A[M,784] @ W1^T   (bf16 3-split, fp32 acc)
// block: 128 rows x 112 cols, BK=16, 8 warps of 32x56
// ---------------------------------------------------------------------------
#define NSTAGE 49   // 784/16

__global__ void __launch_bounds__(256, 2)
gemm_z1_tc(const float* __restrict__ A) {
    __shared__ unsigned Ah[2][128 * 8];
    __shared__ unsigned Al[2][128 * 8];
    __shared__ unsigned Bh[2][112 * 8];
    __shared__ unsigned Bl[2][112 * 8];

    const int tid  = threadIdx.x;
    const int warp = tid >> 5, lane = tid & 31;
    const int g    = lane >> 2, tig = lane & 3;
    const int wm   = (warp >> 1) * 32;      // warp row offset
    const int wn   = (warp & 1) * 56;       // warp col offset
    const int row0 = blockIdx.x * 128;

    float acc[2][7][4];
#pragma unroll
    for (int i = 0; i < 2; i++)
#pragma unroll
        for (int j = 0; j < 7; j++)
#pragma unroll
            for (int q = 0; q < 4; q++) acc[i][j][q] = 0.f;

    // staging registers
    float4 va[2];
    unsigned vbh[4], vbl[4];

    // ---- LDG stage s into regs ----
    auto ldg_stage = [&](int s) {
        int k0 = s * 16;
#pragma unroll
        for (int i = 0; i < 2; i++) {
            int idx = tid + i * 256;            // 0..511
            int r = idx >> 2, q = idx & 3;
            int gr = row0 + r;
            va[i] = (gr < M_ROWS)
                  ? *(const float4*)(A + (size_t)gr * K_DIM + k0 + 4 * q)
                  : make_float4(0.f, 0.f, 0.f, 0.f);
        }
#pragma unroll
        for (int i = 0; i < 4; i++) {
            int idx = tid + i * 256;            // 0..1023, valid < 896
            if (idx < 896) {
                int r = idx >> 3, j = idx & 7;
                size_t off = (size_t)r * (K_DIM / 2) + (k0 >> 1) + j;
                vbh[i] = ((const unsigned*)g_W1h)[off];
                vbl[i] = ((const unsigned*)g_W1l)[off];
            }
        }
    };
    // ---- STS staged regs into buffer ----
    auto sts_stage = [&](int buf) {
#pragma unroll
        for (int i = 0; i < 2; i++) {
            int idx = tid + i * 256;
            int r = idx >> 2, q = idx & 3;
            float4 v = va[i];
            unsigned h0 = pack_bf16x2(v.y, v.x);
            unsigned h1 = pack_bf16x2(v.w, v.z);
            float f0h = __uint_as_float(h0 << 16);
            float f1h = __uint_as_float(h0 & 0xffff0000u);
            float f2h = __uint_as_float(h1 << 16);
            float f3h = __uint_as_float(h1 & 0xffff0000u);
            unsigned l0 = pack_bf16x2(v.y - f1h, v.x - f0h);
            unsigned l1 = pack_bf16x2(v.w - f3h, v.z - f2h);
            int sw = r & 7;
            Ah[buf][r * 8 + ((2 * q)     ^ sw)] = h0;
            Ah[buf][r * 8 + ((2 * q + 1) ^ sw)] = h1;
            Al[buf][r * 8 + ((2 * q)     ^ sw)] = l0;
            Al[buf][r * 8 + ((2 * q + 1) ^ sw)] = l1;
        }
#pragma unroll
        for (int i = 0; i < 4; i++) {
            int idx = tid + i * 256;
            if (idx < 896) {
                int r = idx >> 3, j = idx & 7;
                Bh[buf][r * 8 + (j ^ (r & 7))] = vbh[i];
                Bl[buf][r * 8 + (j ^ (r & 7))] = vbl[i];
            }
        }
    };

    ldg_stage(0);
    sts_stage(0);
    __syncthreads();

#pragma unroll 1
    for (int s = 0; s < NSTAGE; s++) {
        if (s + 1 < NSTAGE) ldg_stage(s + 1);

        const int buf = s & 1;
        // A fragments
        unsigned a_h[2][4], a_l[2][4];
#pragma unroll
        for (int mt = 0; mt < 2; mt++) {
            int r0 = wm + mt * 16 + g, r1 = r0 + 8;
            int s0 = r0 & 7, s1 = r1 & 7;
            a_h[mt][0] = Ah[buf][r0 * 8 + (tig ^ s0)];
            a_h[mt][1] = Ah[buf][r1 * 8 + (tig ^ s1)];
            a_h[mt][2] = Ah[buf][r0 * 8 + ((tig + 4) ^ s0)];
            a_h[mt][3] = Ah[buf][r1 * 8 + ((tig + 4) ^ s1)];
            a_l[mt][0] = Al[buf][r0 * 8 + (tig ^ s0)];
            a_l[mt][1] = Al[buf][r1 * 8 + (tig ^ s1)];
            a_l[mt][2] = Al[buf][r0 * 8 + ((tig + 4) ^ s0)];
            a_l[mt][3] = Al[buf][r1 * 8 + ((tig + 4) ^ s1)];
        }
#pragma unroll
        for (int nt = 0; nt < 7; nt++) {
            int n = wn + nt * 8 + g;
            int sn = n & 7;
            unsigned b0h = Bh[buf][n * 8 + (tig ^ sn)];
            unsigned b1h = Bh[buf][n * 8 + ((tig + 4) ^ sn)];
            unsigned b0l = Bl[buf][n * 8 + (tig ^ sn)];
            unsigned b1l = Bl[buf][n * 8 + ((tig + 4) ^ sn)];
#pragma unroll
            for (int mt = 0; mt < 2; mt++) {
                mma_bf16(acc[mt][nt], a_h[mt], b0h, b1h);   // hi*hi
                mma_bf16(acc[mt][nt], a_h[mt], b0l, b1l);   // hi*lo
                mma_bf16(acc[mt][nt], a_l[mt], b0h, b1h);   // lo*hi
            }
        }

        if (s + 1 < NSTAGE) sts_stage((s + 1) & 1);
        __syncthreads();
    }

    // epilogue
#pragma unroll
    for (int mt = 0; mt < 2; mt++) {
#pragma unroll
        for (int nt = 0; nt < 7; nt++) {
            int c = wn + nt * 8 + 2 * tig;
            if (c >= 99) continue;            // c even; writes c, c+1 (<=99)
            int r0g = row0 + wm + mt * 16 + g;
            if (r0g < M_ROWS) {
                float2 v = make_float2(acc[mt][nt][0], acc[mt][nt][1]);
                *(float2*)(g_z1 + (size_t)r0g * N1 + c) = v;
            }
            if (r0g + 8 < M_ROWS) {
                float2 v = make_float2(acc[mt][nt][2], acc[mt][nt][3]);
                *(float2*)(g_z1 + (size_t)(r0g + 8) * N1 + c) = v;
            }
        }
    }
}

// ---------------------------------------------------------------------------
// HH step — single EX2 + single RCP per gate (unchanged from round 3)
// ---------------------------------------------------------------------------
__device__ __forceinline__ float ex2a(float x) {
    float r; asm("ex2.approx.f32 %0, %1;" : "=f"(r) : "f"(x)); return r;
}
__device__ __forceinline__ float rcpa(float x) {
    float r; asm("rcp.approx.f32 %0, %1;" : "=f"(r) : "f"(x)); return r;
}

#define L9   0.1602994489863f
#define L12  0.1202245867397f
#define L3   0.4808983469589f
#define BH_C 0.0023508962f
#define S0V  9.357622969e-14f

__device__ __forceinline__ void hh_step(float zk, float& V, float& m, float& n, float& h) {
    float mm   = m * m;
    float pow1 = 40.f * (mm * m) * h;
    float nn   = n * n;
    float pow2 = 35.f * (nn * nn);
    float Gs = 0.005f * (pow1 + pow2 + 0.3f);
    float E  = fmaf(pow1, 55.f, fmaf(pow2, -77.f, -19.5f));
    float num = fmaf(V, (1.f - Gs), 0.01f * (E + 1.5f + zk));
    float Vn = num * rcpa(1.f + Gs);

    float dM = Vn + 35.f;
    float uM = ex2a(dM * L9);
    float um1M = uM - 1.f;
    float sM = 0.005f * dM * fmaf(0.182f, uM, 0.124f);
    float mN = fmaf(0.00182f * dM, uM, (um1M - sM) * m) * rcpa(um1M + sM);

    float dN = Vn - 25.f;
    float uN = ex2a(dN * L9);
    float um1N = uN - 1.f;
    float sN = 0.005f * dN * fmaf(0.02f, uN, 0.002f);
    float nN = fmaf(0.0002f * dN, uN, (um1N - sN) * n) * rcpa(um1N + sN);

    float w  = ex2a((Vn + 90.f) * L12);
    float sH = fmaf(0.005f * BH_C, w * w, 0.00125f);
    float hN = fmaf(w - sH, h, 0.0025f) * rcpa(w + sH);

    if (Vn == 25.f)  nN = fmaf(0.99901f, n, 0.0018f) * (1.f / 1.00099f);
    if (Vn == -35.f) mN = fmaf(0.98623f, m, 0.01638f) * (1.f / 1.01377f);

    m = mN; n = nN; h = hN;
    V = Vn;
}

__device__ __forceinline__ float sigmoid_T(float V) {
    return rcpa(1.f + ex2a((20.f - V) * L3));
}

// ---------------------------------------------------------------------------
// K2: layer-1 scan
// ---------------------------------------------------------------------------
__global__ void __launch_bounds__(128, 1)
hh_layer1_kernel() {
    const int idx = blockIdx.x * 128 + threadIdx.x;
    if (idx >= BATCH * N1) return;
    const int b = idx / N1;
    const int c = idx - b * N1;

    const float* zp = g_z1 + (size_t)b * T_STEPS * N1 + c;
    float*       tp = g_T1 + (size_t)b * T_STEPS * N1 + c;

    float V = -70.f, m = 0.f, n = 0.f, h = 1.f;
    tp[0] = S0V;

    float p0 = zp[0];
    float p1 = zp[(size_t)1 * N1];
    float p2 = zp[(size_t)2 * N1];
    float p3 = zp[(size_t)3 * N1];

    for (int s4 = 0; s4 < T_STEPS; s4 += 4) {
#pragma unroll
        for (int j = 0; j < 4; j++) {
            int s = s4 + j;
            float zc = p0;
            p0 = p1; p1 = p2; p2 = p3;
            int pf = s + 4;
            p3 = (pf < T_STEPS) ? zp[(size_t)pf * N1] : 0.f;
            hh_step(zc, V, m, n, h);
            if (s < T_STEPS - 1) tp[(size_t)(s + 1) * N1] = sigmoid_T(V);
        }
    }
}

// ---------------------------------------------------------------------------
// K3: z2t[b*10+o][t] = sum_k T1[b][t][k] * W2[o][k]
// ---------------------------------------------------------------------------
__global__ void __launch_bounds__(256, 4)
z2_kernel(const float* __restrict__ W2) {
    __shared__ float W2s[N1][12];

    const int tid = threadIdx.x;
    for (int i = tid; i < N1 * 12; i += 256) {
        int k = i / 12, o = i - k * 12;
        W2s[k][o] = (o < N2) ? W2[o * N1 + k] : 0.f;
    }
    __syncthreads();

    const int row = blockIdx.x * 256 + tid;
    if (row >= M_ROWS) return;
    const int b = row / T_STEPS;
    const int t = row - b * T_STEPS;

    const float4* tr = (const float4*)(g_T1 + (size_t)row * N1);
    float acc[12];
#pragma unroll
    for (int o = 0; o < 12; o++) acc[o] = 0.f;

#pragma unroll 5
    for (int k4 = 0; k4 < 25; k4++) {
        float4 tv = tr[k4];
        const float* tf = &tv.x;
#pragma unroll
        for (int kk = 0; kk < 4; kk++) {
            int k = k4 * 4 + kk;
            float4 w0 = *(const float4*)&W2s[k][0];
            float4 w1 = *(const float4*)&W2s[k][4];
            float4 w2 = *(const float4*)&W2s[k][8];
            float f = tf[kk];
            acc[0] = fmaf(f, w0.x, acc[0]);  acc[1] = fmaf(f, w0.y, acc[1]);
            acc[2] = fmaf(f, w0.z, acc[2]);  acc[3] = fmaf(f, w0.w, acc[3]);
            acc[4] = fmaf(f, w1.x, acc[4]);  acc[5] = fmaf(f, w1.y, acc[5]);
            acc[6] = fmaf(f, w1.z, acc[6]);  acc[7] = fmaf(f, w1.w, acc[7]);
            acc[8] = fmaf(f, w2.x, acc[8]);  acc[9] = fmaf(f, w2.y, acc[9]);
        }
    }
#pragma unroll
    for (int o = 0; o < N2; o++)
        g_z2t[((size_t)b * N2 + o) * T_STEPS + t] = acc[o];
}

// ---------------------------------------------------------------------------
// K4: layer-2 scan
// ---------------------------------------------------------------------------
__global__ void __launch_bounds__(128, 1)
hh_layer2_kernel(float* __restrict__ out) {
    const int idx = blockIdx.x * 128 + threadIdx.x;
    if (idx >= BATCH * N2) return;
    const int b = idx / N2;
    const int o = idx - b * N2;

    const float4* zrow = (const float4*)(g_z2t + (size_t)idx * T_STEPS);
    float* op = out + ((size_t)b * T_STEPS) * N2 + o;

    float V = -70.f, m = 0.f, n = 0.f, h = 1.f;
    op[0] = S0V;

    float4 buf0 = zrow[0];
    float4 buf1 = zrow[1];

    for (int g = 0; g < T_STEPS / 4; g++) {
        float zv[4] = {buf0.x, buf0.y, buf0.z, buf0.w};
        buf0 = buf1;
        buf1 = (g + 2 < T_STEPS / 4) ? zrow[g + 2] : make_float4(0.f, 0.f, 0.f, 0.f);
#pragma unroll
        for (int j = 0; j < 4; j++) {
            int s = g * 4 + j;
            hh_step(zv[j], V, m, n, h);
            if (s < T_STEPS - 1) op[(size_t)(s + 1) * N2] = sigmoid_T(V);
        }
    }
}

// ---------------------------------------------------------------------------
extern "C" void kernel_launch(void* const* d_in, const int* in_sizes, int n_in,
                              void* d_out, int out_size) {
    const float* batch = (const float*)d_in[0];   // (100, 2000, 784)
    const float* W1    = (const float*)d_in[1];   // (100, 784)
    const float* W2    = (const float*)d_in[2];   // (10, 100)
    float* out = (float*)d_out;                   // (100, 2000, 10)

    w1_convert_kernel<<<(112 * K_DIM + 255) / 256, 256>>>(W1);
    gemm_z1_tc<<<(M_ROWS + 127) / 128, 256>>>(batch);
    hh_layer1_kernel<<<(BATCH * N1 + 127) / 128, 128>>>();
    z2_kernel<<<(M_ROWS + 255) / 256, 256>>>(W2);
    hh_layer2_kernel<<<(BATCH * N2 + 127) / 128, 128>>>(out);
}